// round 11
// baseline (speedup 1.0000x reference)
#include <cuda_runtime.h>
#include <cuda_bf16.h>
#include <cuda_fp16.h>
#include <cstdint>

// ---------------------------------------------------------------------------
// GraphSAGE 3-layer forward, GB300 sm_103a (compute_103 PTX -> mma.sync/HMMA).
//   layer: out = h @ Ws + (segmean_dst h[src]) @ Wn + b  (+relu layers 0,1)
// R11:
//   - k_gemm_fused (layers 1,2): per 32-row tile, gather+aggregate prev layer
//     (hs,hn) directly into A smem (fp16 hi/lo), then fp16 2-pass MMA over all
//     output cols. 2 CTAs/SM -> gather (L2) overlaps MMA (tensor) across CTAs.
//     Deletes k_agg<128> x2 and global ah/al round-trips for h1/h2.
//   - gemm0 stays R10-style (x pre-split, cp.async, column-split)
// ---------------------------------------------------------------------------

#define DINL __device__ __forceinline__

constexpr int NODES_MAX = 100000;
constexpr int EDGES_MAX = 1600000;
constexpr int K_DIM = 128;
constexpr int WST = 136;                 // padded stride (fp16 elems) = 272B
constexpr int WPART = 256 * WST;         // weight image stride (elems)
constexpr int MT = 64;                   // gemm0 row-tile
constexpr int FT = 32;                   // fused row-tile

// scratch (__device__ globals; no allocs allowed)
__device__ int   g_deg[NODES_MAX];
__device__ int   g_roff[NODES_MAX];
__device__ int   g_cursor[NODES_MAX];
__device__ int   g_bsums[256];
__device__ int   g_csr[EDGES_MAX];
__device__ float g_inv[NODES_MAX];
__device__ __align__(16) float  g_hsA[(size_t)NODES_MAX * 128];
__device__ __align__(16) float  g_hsB[(size_t)NODES_MAX * 128];
__device__ __align__(16) __half g_hnA[(size_t)NODES_MAX * 128];
__device__ __align__(16) __half g_hnB[(size_t)NODES_MAX * 128];
__device__ __align__(16) __half g_ah[(size_t)NODES_MAX * 128];
__device__ __align__(16) __half g_al[(size_t)NODES_MAX * 128];
// per layer: single fp16 part = [N up to 256][WST] (N-major)
__device__ __align__(16) __half g_wpad[3][WPART];

// ---------------- helpers ----------------
DINL uint32_t smem_u32(const void* p) {
    uint32_t a;
    asm("{ .reg .u64 t; cvta.to.shared.u64 t, %1; cvt.u32.u64 %0, t; }"
        : "=r"(a) : "l"(p));
    return a;
}
DINL uint32_t pack_hf2(float a, float b) {
    __half2 t = __floats2half2_rn(a, b);
    return *(uint32_t*)&t;
}
DINL float2 hf2f(uint32_t u) {
    __half2 h = *reinterpret_cast<__half2*>(&u);
    return __half22float2(h);
}
DINL void split_hf(float v, float& hi, float& lo) {
    __half h = __float2half(v);
    hi = __half2float(h);
    lo = v - hi;
}
DINL void mma_f16(float (&d)[4], uint32_t a0, uint32_t a1, uint32_t a2, uint32_t a3,
                  uint32_t b0, uint32_t b1) {
    asm volatile(
        "mma.sync.aligned.m16n8k16.row.col.f32.f16.f16.f32 "
        "{%0,%1,%2,%3}, {%4,%5,%6,%7}, {%8,%9}, {%0,%1,%2,%3};"
        : "+f"(d[0]), "+f"(d[1]), "+f"(d[2]), "+f"(d[3])
        : "r"(a0), "r"(a1), "r"(a2), "r"(a3), "r"(b0), "r"(b1));
}
DINL void ldsm_x4(uint32_t& r0, uint32_t& r1, uint32_t& r2, uint32_t& r3, uint32_t addr) {
    asm volatile("ldmatrix.sync.aligned.m8n8.x4.shared.b16 {%0,%1,%2,%3}, [%4];"
                 : "=r"(r0), "=r"(r1), "=r"(r2), "=r"(r3) : "r"(addr));
}
DINL void cp_async16(uint32_t saddr, const void* gptr, int sz) {
    asm volatile("cp.async.cg.shared.global [%0], [%1], 16, %2;"
                 :: "r"(saddr), "l"(gptr), "r"(sz));
}

template <int V>
DINL void vload(float (&v)[V], const float* p) {
    if constexpr (V == 4) {
        float4 t = *(const float4*)p;
        v[0] = t.x; v[1] = t.y; v[2] = t.z; v[3] = t.w;
    } else {
        float2 t = *(const float2*)p;
        v[0] = t.x; v[1] = t.y;
    }
}
template <int V>
DINL void hload(float (&v)[V], const __half* p) {
    if constexpr (V == 4) {
        uint2 u = *(const uint2*)p;
        float2 x = hf2f(u.x), y = hf2f(u.y);
        v[0] = x.x; v[1] = x.y; v[2] = y.x; v[3] = y.y;
    } else {
        uint32_t u = *(const uint32_t*)p;
        float2 x = hf2f(u);
        v[0] = x.x; v[1] = x.y;
    }
}

// ---------------- CSR build ----------------
__global__ void k_count(const int* __restrict__ dst, int E) {
    int i = blockIdx.x * 256 + threadIdx.x;
    int E4 = E >> 2;
    if (i < E4) {
        int4 d = *(const int4*)(dst + i * 4);
        atomicAdd(&g_deg[d.x], 1);
        atomicAdd(&g_deg[d.y], 1);
        atomicAdd(&g_deg[d.z], 1);
        atomicAdd(&g_deg[d.w], 1);
    }
    int t = E4 * 4 + i;
    if (t < E) atomicAdd(&g_deg[dst[t]], 1);
}

__global__ void k_scan1(int n) {
    __shared__ int sh[256];
    int t = threadIdx.x;
    int i0 = blockIdx.x * 1024 + t * 4;
    int v0 = (i0 + 0 < n) ? g_deg[i0 + 0] : 0;
    int v1 = (i0 + 1 < n) ? g_deg[i0 + 1] : 0;
    int v2 = (i0 + 2 < n) ? g_deg[i0 + 2] : 0;
    int v3 = (i0 + 3 < n) ? g_deg[i0 + 3] : 0;
    int p1 = v0, p2 = v0 + v1, p3 = p2 + v2, tot = p3 + v3;
    sh[t] = tot;
    __syncthreads();
    int incl = tot;
    for (int off = 1; off < 256; off <<= 1) {
        int x = (t >= off) ? sh[t - off] : 0;
        __syncthreads();
        incl += x;
        sh[t] = incl;
        __syncthreads();
    }
    int ex = incl - tot;
    if (i0 + 0 < n) g_roff[i0 + 0] = ex;
    if (i0 + 1 < n) g_roff[i0 + 1] = ex + p1;
    if (i0 + 2 < n) g_roff[i0 + 2] = ex + p2;
    if (i0 + 3 < n) g_roff[i0 + 3] = ex + p3;
    if (t == 255) g_bsums[blockIdx.x] = incl;
}

__global__ void k_scan23(int n, int nb) {
    __shared__ int sh[256];
    __shared__ int ex[256];
    int t = threadIdx.x;
    int v = (t < nb) ? g_bsums[t] : 0;
    sh[t] = v;
    __syncthreads();
    int incl = v;
    for (int off = 1; off < 256; off <<= 1) {
        int x = (t >= off) ? sh[t - off] : 0;
        __syncthreads();
        incl += x;
        sh[t] = incl;
        __syncthreads();
    }
    ex[t] = incl - v;
    __syncthreads();
    int i = blockIdx.x * 256 + t;
    if (i >= n) return;
    int r = g_roff[i] + ex[i >> 10];
    g_roff[i] = r;
    g_cursor[i] = r;
    g_inv[i] = 1.0f / fmaxf((float)g_deg[i], 1.0f);
}

__global__ void k_fill(const int* __restrict__ src, const int* __restrict__ dst, int E) {
    int i = blockIdx.x * 256 + threadIdx.x;
    int E4 = E >> 2;
    if (i < E4) {
        int4 d = *(const int4*)(dst + i * 4);
        int4 s = *(const int4*)(src + i * 4);
        int p0 = atomicAdd(&g_cursor[d.x], 1);
        int p1 = atomicAdd(&g_cursor[d.y], 1);
        int p2 = atomicAdd(&g_cursor[d.z], 1);
        int p3 = atomicAdd(&g_cursor[d.w], 1);
        g_csr[p0] = s.x; g_csr[p1] = s.y; g_csr[p2] = s.z; g_csr[p3] = s.w;
    }
    int t = E4 * 4 + i;
    if (t < E) {
        int p = atomicAdd(&g_cursor[dst[t]], 1);
        g_csr[p] = src[t];
    }
}

// ---------------- fused weight conversion (all 3 layers, single fp16 part) ----------------
__global__ void k_wconv_all(const float* __restrict__ ws0, const float* __restrict__ wn0,
                            const float* __restrict__ ws1, const float* __restrict__ wn1,
                            const float* __restrict__ ws2, const float* __restrict__ wn2) {
    int idx = blockIdx.x * 256 + threadIdx.x;
    int NOUT;
    const float *ws, *wn;
    __half* img;
    if (idx < 32768) { NOUT = 256; ws = ws0; wn = wn0; img = g_wpad[0]; }
    else if (idx < 65536) { idx -= 32768; NOUT = 256; ws = ws1; wn = wn1; img = g_wpad[1]; }
    else if (idx < 81920) { idx -= 65536; NOUT = 128; ws = ws2; wn = wn2; img = g_wpad[2]; }
    else return;
    const int HALF = NOUT / 2;
    int nrow = idx / K_DIM, k = idx % K_DIM;
    float v = (nrow < HALF) ? ws[k * HALF + nrow] : wn[k * HALF + (nrow - HALF)];
    img[nrow * WST + k] = __float2half(v);
}

// ---------------- x -> fp16 hi/lo ----------------
__global__ void k_xconv(const float* __restrict__ x, int total4) {
    int i = blockIdx.x * 256 + threadIdx.x;
    if (i >= total4) return;
    float4 v = *(const float4*)(x + (size_t)i * 4);
    float h0, l0, h1, l1, h2, l2, h3, l3;
    split_hf(v.x, h0, l0); split_hf(v.y, h1, l1);
    split_hf(v.z, h2, l2); split_hf(v.w, h3, l3);
    *(uint2*)(g_ah + (size_t)i * 4) = make_uint2(pack_hf2(h0, h1), pack_hf2(h2, h3));
    *(uint2*)(g_al + (size_t)i * 4) = make_uint2(pack_hf2(l0, l1), pack_hf2(l2, l3));
}

// ---------------- layer-0 GEMM (R10-style: column-split, cp.async, 2 CTA/SM) ----------------
template <int NOUT>
__global__ void __launch_bounds__(256, 2)
k_gemm_mma(const __half* __restrict__ Ah, const __half* __restrict__ Al,
           const __half* __restrict__ Wimg, float* __restrict__ hs,
           __half* __restrict__ hn, int nrows, int ntiles) {
    constexpr int HALFN = NOUT / 2;
    constexpr int ABYTES = MT * WST * 2;
    constexpr int OFF_W = 4 * ABYTES;
    constexpr int TILES = HALFN / 16;
    extern __shared__ __align__(16) uint8_t smem[];

    const int tid = threadIdx.x;
    const int cg = blockIdx.x & 1;
    const int stride = gridDim.x >> 1;
    const int t0 = blockIdx.x >> 1;
    const uint32_t sb = smem_u32(smem);

    for (int i = tid; i < HALFN * 17; i += 256) {
        int r = i / 17, c = i - r * 17;
        const uint8_t* gp =
            (const uint8_t*)(Wimg + (size_t)(cg * HALFN + r) * WST) + c * 16;
        *(uint4*)(smem + OFF_W + r * (WST * 2) + c * 16) = *(const uint4*)gp;
    }

    auto stageA = [&](int tile, int buf) {
        const int m0 = tile * MT;
        const uint32_t base = sb + buf * (2 * ABYTES);
        for (int i = tid; i < 2048; i += 256) {
            int part = i >> 10;
            int r = (i >> 4) & 63;
            int c = i & 15;
            int row = m0 + r;
            const __half* gp = (part ? Al : Ah) + (size_t)row * K_DIM + c * 8;
            cp_async16(base + part * ABYTES + r * (WST * 2) + c * 16, gp,
                       (row < nrows) ? 16 : 0);
        }
        asm volatile("cp.async.commit_group;" ::: "memory");
    };

    const int wid = tid >> 5, lane = tid & 31;
    const int qid = lane >> 2, tig = lane & 3;
    const int rwarp = (wid & 3) * 16;
    const int colsub = (wid >> 2) * (HALFN / 2);

    const int arow = rwarp + (lane & 15);
    const uint32_t aaddr = sb + (uint32_t)arow * (WST * 2) + ((uint32_t)(lane >> 4) << 4);
    const int nrl = colsub + (lane & 7) + ((lane >> 4) << 3);
    const uint32_t bbase = sb + OFF_W + (uint32_t)nrl * (WST * 2) +
                           ((uint32_t)((lane >> 3) & 1) << 4);

    if (t0 < ntiles) stageA(t0, 0);
    int cur = 0;
    for (int tile = t0; tile < ntiles; tile += stride) {
        int nxt = tile + stride;
        if (nxt < ntiles) {
            stageA(nxt, cur ^ 1);
            asm volatile("cp.async.wait_group 1;" ::: "memory");
        } else {
            asm volatile("cp.async.wait_group 0;" ::: "memory");
        }
        __syncthreads();

        float acc[TILES][4];
#pragma unroll
        for (int t = 0; t < TILES; t++)
#pragma unroll
            for (int q = 0; q < 4; q++) acc[t][q] = 0.f;

        const uint32_t aH = aaddr + cur * (2 * ABYTES);
        const uint32_t aL = aH + ABYTES;

#pragma unroll 4
        for (int k0 = 0; k0 < K_DIM; k0 += 16) {
            uint32_t h0, h1, h2, h3, l0, l1, l2, l3;
            ldsm_x4(h0, h1, h2, h3, aH + k0 * 2);
            ldsm_x4(l0, l1, l2, l3, aL + k0 * 2);
#pragma unroll
            for (int tp = 0; tp < TILES / 2; tp++) {
                const uint32_t boff = tp * (16 * WST * 2) + k0 * 2;
                uint32_t w0, w1, w2, w3;
                ldsm_x4(w0, w1, w2, w3, bbase + boff);
                mma_f16(acc[2 * tp + 0], h0, h1, h2, h3, w0, w1);
                mma_f16(acc[2 * tp + 1], h0, h1, h2, h3, w2, w3);
                mma_f16(acc[2 * tp + 0], l0, l1, l2, l3, w0, w1);
                mma_f16(acc[2 * tp + 1], l0, l1, l2, l3, w2, w3);
            }
        }

        const int r0 = tile * MT + rwarp + qid;
        const bool ok0 = r0 < nrows, ok1 = (r0 + 8) < nrows;
        if (cg == 0) {
#pragma unroll
            for (int t = 0; t < TILES; t++) {
                int col = colsub + t * 8 + tig * 2;
                if (ok0) *(float2*)&hs[(size_t)r0 * HALFN + col] = make_float2(acc[t][0], acc[t][1]);
                if (ok1) *(float2*)&hs[(size_t)(r0 + 8) * HALFN + col] = make_float2(acc[t][2], acc[t][3]);
            }
        } else {
#pragma unroll
            for (int t = 0; t < TILES; t++) {
                int col = colsub + t * 8 + tig * 2;
                if (ok0) *(uint32_t*)&hn[(size_t)r0 * HALFN + col] = pack_hf2(acc[t][0], acc[t][1]);
                if (ok1) *(uint32_t*)&hn[(size_t)(r0 + 8) * HALFN + col] = pack_hf2(acc[t][2], acc[t][3]);
            }
        }
        __syncthreads();
        cur ^= 1;
    }
}

// ---------------- fused agg+GEMM (layers 1,2) ----------------
// Per 32-row tile: gather/aggregate prev layer into A smem (fp16 hi/lo, exact
// split of y = relu(hs + inv*sum(hn[nbr]) + b)), then fp16 2-pass MMA over all
// NOUT cols. grid 296 (2 CTA/SM), 256 thr = 8 warps = 2 row-strips x 4 col grps.
template <int NOUT>
__global__ void __launch_bounds__(256, 2)
k_gemm_fused(const float* __restrict__ hs_in, const __half* __restrict__ hn_in,
             const float* __restrict__ bias, const __half* __restrict__ Wimg,
             float* __restrict__ hs_out, __half* __restrict__ hn_out,
             int nrows, int ntiles) {
    constexpr int HALF = NOUT / 2;
    constexpr int ABYTES = FT * WST * 2;      // 8704 per A part
    constexpr int OFF_W = 2 * ABYTES;
    constexpr int CW = NOUT / 4;              // cols per warp (64 / 32)
    constexpr int NP = CW / 16;               // B ldsm pairs per warp
    extern __shared__ __align__(16) uint8_t smem[];

    const int tid = threadIdx.x;
    const uint32_t sb = smem_u32(smem);

    // stage W once (all NOUT rows)
    for (int i = tid; i < NOUT * 17; i += 256) {
        int r = i / 17, c = i - r * 17;
        const uint8_t* gp = (const uint8_t*)(Wimg + (size_t)r * WST) + c * 16;
        *(uint4*)(smem + OFF_W + r * (WST * 2) + c * 16) = *(const uint4*)gp;
    }

    const int wid = tid >> 5, lane = tid & 31;
    const int qid = lane >> 2, tig = lane & 3;
    const int rwarp = (wid & 1) * 16;
    const int colgrp = wid >> 1;              // 0..3

    const int arow = rwarp + (lane & 15);
    const uint32_t aaddr = sb + (uint32_t)arow * (WST * 2) + ((uint32_t)(lane >> 4) << 4);
    const int nrl = colgrp * CW + (lane & 7) + ((lane >> 4) << 3);
    const uint32_t bbase = sb + OFF_W + (uint32_t)nrl * (WST * 2) +
                           ((uint32_t)((lane >> 3) & 1) << 4);

    for (int tile = blockIdx.x; tile < ntiles; tile += gridDim.x) {
        const int m0 = tile * FT;

        // ---- gather + aggregate phase: warp handles 4 rows ----
#pragma unroll 1
        for (int i = 0; i < 4; i++) {
            const int r = wid * 4 + i;
            const int row = m0 + r;
            uint2 hi2 = make_uint2(0, 0), lo2 = make_uint2(0, 0);
            if (row < nrows) {
                float acc[4] = {0.f, 0.f, 0.f, 0.f};
                const int start = g_roff[row];
                const int d = g_deg[row];
                const int* __restrict__ cp = g_csr + start;
                int t = 0;
#pragma unroll 1
                for (; t + 4 <= d; t += 4) {
                    int j0 = __ldg(cp + t + 0);
                    int j1 = __ldg(cp + t + 1);
                    int j2 = __ldg(cp + t + 2);
                    int j3 = __ldg(cp + t + 3);
                    float v0[4], v1[4], v2[4], v3[4];
                    hload<4>(v0, &hn_in[(size_t)j0 * 128 + lane * 4]);
                    hload<4>(v1, &hn_in[(size_t)j1 * 128 + lane * 4]);
                    hload<4>(v2, &hn_in[(size_t)j2 * 128 + lane * 4]);
                    hload<4>(v3, &hn_in[(size_t)j3 * 128 + lane * 4]);
#pragma unroll
                    for (int c = 0; c < 4; c++) acc[c] += (v0[c] + v1[c]) + (v2[c] + v3[c]);
                }
                for (; t < d; t++) {
                    int jj = __ldg(cp + t);
                    float vv[4];
                    hload<4>(vv, &hn_in[(size_t)jj * 128 + lane * 4]);
#pragma unroll
                    for (int c = 0; c < 4; c++) acc[c] += vv[c];
                }
                const float inv = g_inv[row];
                float sf[4], bb[4];
                vload<4>(sf, hs_in + (size_t)row * 128 + lane * 4);
                vload<4>(bb, bias + lane * 4);
                float h[4], l[4];
#pragma unroll
                for (int c = 0; c < 4; c++) {
                    float y = fmaxf(fmaf(inv, acc[c], sf[c]) + bb[c], 0.f);
                    split_hf(y, h[c], l[c]);
                }
                hi2 = make_uint2(pack_hf2(h[0], h[1]), pack_hf2(h[2], h[3]));
                lo2 = make_uint2(pack_hf2(l[0], l[1]), pack_hf2(l[2], l[3]));
            }
            *(uint2*)(smem + r * (WST * 2) + lane * 8) = hi2;
            *(uint2*)(smem + ABYTES + r * (WST * 2) + lane * 8) = lo2;
        }
        __syncthreads();   // gather done (also covers initial W staging)

        // ---- MMA phase ----
        float acc[2 * NP][4];
#pragma unroll
        for (int t = 0; t < 2 * NP; t++)
#pragma unroll
            for (int q = 0; q < 4; q++) acc[t][q] = 0.f;

#pragma unroll 4
        for (int k0 = 0; k0 < K_DIM; k0 += 16) {
            uint32_t h0, h1, h2, h3, l0, l1, l2, l3;
            ldsm_x4(h0, h1, h2, h3, aaddr + k0 * 2);
            ldsm_x4(l0, l1, l2, l3, aaddr + ABYTES + k0 * 2);
#pragma unroll
            for (int tp = 0; tp < NP; tp++) {
                const uint32_t boff = tp * (16 * WST * 2) + k0 * 2;
                uint32_t w0, w1, w2, w3;
                ldsm_x4(w0, w1, w2, w3, bbase + boff);
                mma_f16(acc[2 * tp + 0], h0, h1, h2, h3, w0, w1);
                mma_f16(acc[2 * tp + 1], h0, h1, h2, h3, w2, w3);
                mma_f16(acc[2 * tp + 0], l0, l1, l2, l3, w0, w1);
                mma_f16(acc[2 * tp + 1], l0, l1, l2, l3, w2, w3);
            }
        }

        // ---- epilogue: cols < HALF -> hs_out (fp32), else hn_out (fp16) ----
        const int r0 = m0 + rwarp + qid;
        const bool ok0 = r0 < nrows, ok1 = (r0 + 8) < nrows;
#pragma unroll
        for (int t = 0; t < 2 * NP; t++) {
            int col = colgrp * CW + t * 8 + tig * 2;
            if (col < HALF) {
                if (ok0) *(float2*)&hs_out[(size_t)r0 * HALF + col] = make_float2(acc[t][0], acc[t][1]);
                if (ok1) *(float2*)&hs_out[(size_t)(r0 + 8) * HALF + col] = make_float2(acc[t][2], acc[t][3]);
            } else {
                int c2 = col - HALF;
                if (ok0) *(uint32_t*)&hn_out[(size_t)r0 * HALF + c2] = pack_hf2(acc[t][0], acc[t][1]);
                if (ok1) *(uint32_t*)&hn_out[(size_t)(r0 + 8) * HALF + c2] = pack_hf2(acc[t][2], acc[t][3]);
            }
        }
        __syncthreads();   // MMA reads done before next gather overwrites A
    }
}

// ---------------- final aggregation (layer 2 output, 64-wide, fp32 out) ----------------
__global__ void k_agg_out(const float* __restrict__ hs, const __half* __restrict__ hn,
                          const float* __restrict__ bias, float* __restrict__ outf, int n) {
    constexpr int W = 64, V = 2;
    int w = (blockIdx.x * blockDim.x + threadIdx.x) >> 5;
    if (w >= n) return;
    int lane = threadIdx.x & 31;

    float acc[V] = {0.f, 0.f};
    const int start = g_roff[w];
    const int d = g_deg[w];
    const int* __restrict__ cp = g_csr + start;
    int t = 0;
#pragma unroll 1
    for (; t + 4 <= d; t += 4) {
        int j0 = __ldg(cp + t + 0);
        int j1 = __ldg(cp + t + 1);
        int j2 = __ldg(cp + t + 2);
        int j3 = __ldg(cp + t + 3);
        float v0[V], v1[V], v2[V], v3[V];
        hload<V>(v0, &hn[(size_t)j0 * W + lane * V]);
        hload<V>(v1, &hn[(size_t)j1 * W + lane * V]);
        hload<V>(v2, &hn[(size_t)j2 * W + lane * V]);
        hload<V>(v3, &hn[(size_t)j3 * W + lane * V]);
#pragma unroll
        for (int c = 0; c < V; c++) acc[c] += (v0[c] + v1[c]) + (v2[c] + v3[c]);
    }
    for (; t < d; t++) {
        int jj = __ldg(cp + t);
        float vv[V];
        hload<V>(vv, &hn[(size_t)jj * W + lane * V]);
#pragma unroll
        for (int c = 0; c < V; c++) acc[c] += vv[c];
    }

    float inv = g_inv[w];
    float sf[V], bb[V];
    vload<V>(sf, &hs[(size_t)w * W + lane * V]);
    vload<V>(bb, &bias[lane * V]);
    float2 o;
    o.x = fmaf(inv, acc[0], sf[0]) + bb[0];
    o.y = fmaf(inv, acc[1], sf[1]) + bb[1];
    *(float2*)(outf + (size_t)w * W + lane * V) = o;
}

// ---------------------------------------------------------------------------
extern "C" void kernel_launch(void* const* d_in, const int* in_sizes, int n_in,
                              void* d_out, int out_size) {
    const float* x   = (const float*)d_in[0];
    const int*   src = (const int*)d_in[1];
    const int*   dst = (const int*)d_in[2];
    const float* ws0 = (const float*)d_in[3];
    const float* wn0 = (const float*)d_in[4];
    const float* b0  = (const float*)d_in[5];
    const float* ws1 = (const float*)d_in[6];
    const float* wn1 = (const float*)d_in[7];
    const float* b1  = (const float*)d_in[8];
    const float* ws2 = (const float*)d_in[9];
    const float* wn2 = (const float*)d_in[10];
    const float* b2  = (const float*)d_in[11];

    const int n = in_sizes[0] / K_DIM;
    const int E = in_sizes[1];

    void *p_deg, *p_hsA, *p_hsB, *p_hnA, *p_hnB, *p_ah, *p_al, *p_w;
    cudaGetSymbolAddress(&p_deg, g_deg);
    cudaGetSymbolAddress(&p_hsA, g_hsA);
    cudaGetSymbolAddress(&p_hsB, g_hsB);
    cudaGetSymbolAddress(&p_hnA, g_hnA);
    cudaGetSymbolAddress(&p_hnB, g_hnB);
    cudaGetSymbolAddress(&p_ah, g_ah);
    cudaGetSymbolAddress(&p_al, g_al);
    cudaGetSymbolAddress(&p_w, g_wpad);
    float* hsA = (float*)p_hsA;
    float* hsB = (float*)p_hsB;
    __half* hnA = (__half*)p_hnA;
    __half* hnB = (__half*)p_hnB;
    const __half* ah = (const __half*)p_ah;
    const __half* al = (const __half*)p_al;
    __half* wimg = (__half*)p_w;
    constexpr size_t WSLOT = WPART;

    static cudaStream_t s2 = nullptr;
    static cudaEvent_t evF = nullptr, evJ = nullptr;
    if (!s2) {
        cudaStreamCreateWithFlags(&s2, cudaStreamNonBlocking);
        cudaEventCreateWithFlags(&evF, cudaEventDisableTiming);
        cudaEventCreateWithFlags(&evJ, cudaEventDisableTiming);
    }

    constexpr int ABYTES0 = MT * WST * 2;
    constexpr int SMEM_G0 = 4 * ABYTES0 + 128 * WST * 2;       // 104448
    constexpr int ABYTESF = FT * WST * 2;
    constexpr int SMEM_F256 = 2 * ABYTESF + 256 * WST * 2;     // 87040
    constexpr int SMEM_F128 = 2 * ABYTESF + 128 * WST * 2;     // 52224
    cudaFuncSetAttribute(k_gemm_mma<256>, cudaFuncAttributeMaxDynamicSharedMemorySize, SMEM_G0);
    cudaFuncSetAttribute(k_gemm_fused<256>, cudaFuncAttributeMaxDynamicSharedMemorySize, SMEM_F256);
    cudaFuncSetAttribute(k_gemm_fused<128>, cudaFuncAttributeMaxDynamicSharedMemorySize, SMEM_F128);

    const int ntiles0 = (n + MT - 1) / MT;
    const int ntilesF = (n + FT - 1) / FT;
    const int eb = (E / 4 + 255) / 256;
    const int nb1 = (n + 1023) / 1024;
    const int ab = (n + 7) / 8;
    const int total4 = n * (K_DIM / 4);

    // fork: CSR on s2; submission order puts gemm0 at ncu capture slot 4
    cudaEventRecord(evF, 0);
    cudaStreamWaitEvent(s2, evF, 0);
    cudaMemsetAsync(p_deg, 0, n * sizeof(int), s2);
    k_count<<<eb, 256, 0, s2>>>(dst, E);                                   // #1
    k_wconv_all<<<(81920 + 255) / 256, 256>>>(ws0, wn0, ws1, wn1, ws2, wn2); // #2
    k_xconv<<<(total4 + 255) / 256, 256>>>(x, total4);                     // #3
    k_gemm_mma<256><<<296, 256, SMEM_G0>>>(ah, al, wimg + 0 * WSLOT, hsA, hnA, n, ntiles0); // #4
    k_scan1<<<nb1, 256, 0, s2>>>(n);
    k_scan23<<<(n + 255) / 256, 256, 0, s2>>>(n, nb1);
    k_fill<<<eb, 256, 0, s2>>>(src, dst, E);
    cudaEventRecord(evJ, s2);
    cudaStreamWaitEvent(0, evJ, 0);

    // fused layers 1, 2
    k_gemm_fused<256><<<296, 256, SMEM_F256>>>(hsA, hnA, b0, wimg + 1 * WSLOT, hsB, hnB, n, ntilesF);
    k_gemm_fused<128><<<296, 256, SMEM_F128>>>(hsB, hnB, b1, wimg + 2 * WSLOT, hsA, hnA, n, ntilesF);
    // final aggregation (64-wide, + b2, no relu)
    k_agg_out<<<ab, 256>>>(hsA, hnA, b2, (float*)d_out, n);
}

// round 12
// speedup vs baseline: 1.5332x; 1.5332x over previous
#include <cuda_runtime.h>
#include <cuda_bf16.h>
#include <cuda_fp16.h>
#include <cstdint>

// ---------------------------------------------------------------------------
// GraphSAGE 3-layer forward, GB300 sm_103a (compute_103 PTX -> mma.sync/HMMA).
//   layer: out = h @ Ws + (segmean_dst h[src]) @ Wn + b  (+relu layers 0,1)
// R12 = R10 revert (R11 fusion regressed) + two micro-opts:
//   - agg gather unrolled to 8 outstanding loads (was 4) -> closer to LTS cap
//   - wconv+xconv merged into one conversion kernel (one less launch)
//   Core (from R10): fp16 exact-A 2-pass GEMM, column-split persistent,
//   cp.async A double-buffer, 2 CTA/SM, CSR built on a forked stream.
// ---------------------------------------------------------------------------

#define DINL __device__ __forceinline__

constexpr int NODES_MAX = 100000;
constexpr int EDGES_MAX = 1600000;
constexpr int K_DIM = 128;
constexpr int WST = 136;                 // padded stride (fp16 elems) = 272B
constexpr int WPART = 256 * WST;         // weight image stride (elems)
constexpr int MT = 64;                   // GEMM row-tile

// scratch (__device__ globals; no allocs allowed)
__device__ int   g_deg[NODES_MAX];
__device__ int   g_roff[NODES_MAX];
__device__ int   g_cursor[NODES_MAX];
__device__ int   g_bsums[256];
__device__ int   g_csr[EDGES_MAX];
__device__ float g_inv[NODES_MAX];
__device__ __align__(16) float g_hs[(size_t)NODES_MAX * 128];
__device__ __align__(16) __half g_hn[(size_t)NODES_MAX * 128];
__device__ __align__(16) __half g_ah[(size_t)NODES_MAX * 128];
__device__ __align__(16) __half g_al[(size_t)NODES_MAX * 128];
// per layer: single fp16 part = [N up to 256][WST] (N-major)
__device__ __align__(16) __half g_wpad[3][WPART];

// ---------------- helpers ----------------
DINL uint32_t smem_u32(const void* p) {
    uint32_t a;
    asm("{ .reg .u64 t; cvta.to.shared.u64 t, %1; cvt.u32.u64 %0, t; }"
        : "=r"(a) : "l"(p));
    return a;
}
DINL uint32_t pack_hf2(float a, float b) {
    __half2 t = __floats2half2_rn(a, b);
    return *(uint32_t*)&t;
}
DINL float2 hf2f(uint32_t u) {
    __half2 h = *reinterpret_cast<__half2*>(&u);
    return __half22float2(h);
}
// fp16 hi/lo split: hi = fp16(v), lo = v - hi
DINL void split_hf(float v, float& hi, float& lo) {
    __half h = __float2half(v);
    hi = __half2float(h);
    lo = v - hi;
}
DINL void mma_f16(float (&d)[4], uint32_t a0, uint32_t a1, uint32_t a2, uint32_t a3,
                  uint32_t b0, uint32_t b1) {
    asm volatile(
        "mma.sync.aligned.m16n8k16.row.col.f32.f16.f16.f32 "
        "{%0,%1,%2,%3}, {%4,%5,%6,%7}, {%8,%9}, {%0,%1,%2,%3};"
        : "+f"(d[0]), "+f"(d[1]), "+f"(d[2]), "+f"(d[3])
        : "r"(a0), "r"(a1), "r"(a2), "r"(a3), "r"(b0), "r"(b1));
}
DINL void ldsm_x4(uint32_t& r0, uint32_t& r1, uint32_t& r2, uint32_t& r3, uint32_t addr) {
    asm volatile("ldmatrix.sync.aligned.m8n8.x4.shared.b16 {%0,%1,%2,%3}, [%4];"
                 : "=r"(r0), "=r"(r1), "=r"(r2), "=r"(r3) : "r"(addr));
}
DINL void cp_async16(uint32_t saddr, const void* gptr, int sz) {
    asm volatile("cp.async.cg.shared.global [%0], [%1], 16, %2;"
                 :: "r"(saddr), "l"(gptr), "r"(sz));
}

template <int V>
DINL void vload(float (&v)[V], const float* p) {
    if constexpr (V == 4) {
        float4 t = *(const float4*)p;
        v[0] = t.x; v[1] = t.y; v[2] = t.z; v[3] = t.w;
    } else {
        float2 t = *(const float2*)p;
        v[0] = t.x; v[1] = t.y;
    }
}
template <int V>
DINL void hload(float (&v)[V], const __half* p) {
    if constexpr (V == 4) {
        uint2 u = *(const uint2*)p;
        float2 x = hf2f(u.x), y = hf2f(u.y);
        v[0] = x.x; v[1] = x.y; v[2] = y.x; v[3] = y.y;
    } else {
        uint32_t u = *(const uint32_t*)p;
        float2 x = hf2f(u);
        v[0] = x.x; v[1] = x.y;
    }
}

// ---------------- CSR build ----------------
__global__ void k_count(const int* __restrict__ dst, int E) {
    int i = blockIdx.x * 256 + threadIdx.x;
    int E4 = E >> 2;
    if (i < E4) {
        int4 d = *(const int4*)(dst + i * 4);
        atomicAdd(&g_deg[d.x], 1);
        atomicAdd(&g_deg[d.y], 1);
        atomicAdd(&g_deg[d.z], 1);
        atomicAdd(&g_deg[d.w], 1);
    }
    int t = E4 * 4 + i;
    if (t < E) atomicAdd(&g_deg[dst[t]], 1);
}

__global__ void k_scan1(int n) {
    __shared__ int sh[256];
    int t = threadIdx.x;
    int i0 = blockIdx.x * 1024 + t * 4;
    int v0 = (i0 + 0 < n) ? g_deg[i0 + 0] : 0;
    int v1 = (i0 + 1 < n) ? g_deg[i0 + 1] : 0;
    int v2 = (i0 + 2 < n) ? g_deg[i0 + 2] : 0;
    int v3 = (i0 + 3 < n) ? g_deg[i0 + 3] : 0;
    int p1 = v0, p2 = v0 + v1, p3 = p2 + v2, tot = p3 + v3;
    sh[t] = tot;
    __syncthreads();
    int incl = tot;
    for (int off = 1; off < 256; off <<= 1) {
        int x = (t >= off) ? sh[t - off] : 0;
        __syncthreads();
        incl += x;
        sh[t] = incl;
        __syncthreads();
    }
    int ex = incl - tot;
    if (i0 + 0 < n) g_roff[i0 + 0] = ex;
    if (i0 + 1 < n) g_roff[i0 + 1] = ex + p1;
    if (i0 + 2 < n) g_roff[i0 + 2] = ex + p2;
    if (i0 + 3 < n) g_roff[i0 + 3] = ex + p3;
    if (t == 255) g_bsums[blockIdx.x] = incl;
}

// merged scan2+scan3: every block redundantly scans g_bsums (nb <= 256)
__global__ void k_scan23(int n, int nb) {
    __shared__ int sh[256];
    __shared__ int ex[256];
    int t = threadIdx.x;
    int v = (t < nb) ? g_bsums[t] : 0;
    sh[t] = v;
    __syncthreads();
    int incl = v;
    for (int off = 1; off < 256; off <<= 1) {
        int x = (t >= off) ? sh[t - off] : 0;
        __syncthreads();
        incl += x;
        sh[t] = incl;
        __syncthreads();
    }
    ex[t] = incl - v;
    __syncthreads();
    int i = blockIdx.x * 256 + t;
    if (i >= n) return;
    int r = g_roff[i] + ex[i >> 10];
    g_roff[i] = r;
    g_cursor[i] = r;
    g_inv[i] = 1.0f / fmaxf((float)g_deg[i], 1.0f);
}

__global__ void k_fill(const int* __restrict__ src, const int* __restrict__ dst, int E) {
    int i = blockIdx.x * 256 + threadIdx.x;
    int E4 = E >> 2;
    if (i < E4) {
        int4 d = *(const int4*)(dst + i * 4);
        int4 s = *(const int4*)(src + i * 4);
        int p0 = atomicAdd(&g_cursor[d.x], 1);
        int p1 = atomicAdd(&g_cursor[d.y], 1);
        int p2 = atomicAdd(&g_cursor[d.z], 1);
        int p3 = atomicAdd(&g_cursor[d.w], 1);
        g_csr[p0] = s.x; g_csr[p1] = s.y; g_csr[p2] = s.z; g_csr[p3] = s.w;
    }
    int t = E4 * 4 + i;
    if (t < E) {
        int p = atomicAdd(&g_cursor[dst[t]], 1);
        g_csr[p] = src[t];
    }
}

// ---------------- merged conversions: weights (fp16 images) + x (fp16 hi/lo) ----------------
// idx < 81920: weight element; else x float4 element (idx - 81920 < total4)
__global__ void k_conv_all(const float* __restrict__ ws0, const float* __restrict__ wn0,
                           const float* __restrict__ ws1, const float* __restrict__ wn1,
                           const float* __restrict__ ws2, const float* __restrict__ wn2,
                           const float* __restrict__ x, int total4) {
    int idx = blockIdx.x * 256 + threadIdx.x;
    if (idx < 81920) {
        int NOUT;
        const float *ws, *wn;
        __half* img;
        if (idx < 32768) { NOUT = 256; ws = ws0; wn = wn0; img = g_wpad[0]; }
        else if (idx < 65536) { idx -= 32768; NOUT = 256; ws = ws1; wn = wn1; img = g_wpad[1]; }
        else { idx -= 65536; NOUT = 128; ws = ws2; wn = wn2; img = g_wpad[2]; }
        const int HALF = NOUT / 2;
        int nrow = idx / K_DIM, k = idx % K_DIM;
        float v = (nrow < HALF) ? ws[k * HALF + nrow] : wn[k * HALF + (nrow - HALF)];
        img[nrow * WST + k] = __float2half(v);
    } else {
        int i = idx - 81920;
        if (i >= total4) return;
        float4 v = *(const float4*)(x + (size_t)i * 4);
        float h0, l0, h1, l1, h2, l2, h3, l3;
        split_hf(v.x, h0, l0); split_hf(v.y, h1, l1);
        split_hf(v.z, h2, l2); split_hf(v.w, h3, l3);
        *(uint2*)(g_ah + (size_t)i * 4) = make_uint2(pack_hf2(h0, h1), pack_hf2(h2, h3));
        *(uint2*)(g_al + (size_t)i * 4) = make_uint2(pack_hf2(l0, l1), pack_hf2(l2, l3));
    }
}

// ---------------- column-split persistent GEMM, fp16 2-pass, 2 CTA/SM ----------------
// grid = 296: cg = bid&1 selects output-column half (0 -> hs fp32, 1 -> hn fp16),
// t0 = bid>>1, stride 148. 64-row tiles, 256 threads = 8 warps =
// 4 row-strips(16) x 2 col subgroups of HALFN/2. C = Ah@W + Al@W (W frags shared).
template <int NOUT>
__global__ void __launch_bounds__(256, 2)
k_gemm_mma(const __half* __restrict__ Ah, const __half* __restrict__ Al,
           const __half* __restrict__ Wimg, float* __restrict__ hs,
           __half* __restrict__ hn, int nrows, int ntiles) {
    constexpr int HALFN = NOUT / 2;           // output width of each dest
    constexpr int ABYTES = MT * WST * 2;      // 17408 per A part
    constexpr int OFF_W = 4 * ABYTES;         // A: 2 bufs x 2 parts
    constexpr int TILES = HALFN / 16;         // n8 tiles per warp
    extern __shared__ __align__(16) uint8_t smem[];

    const int tid = threadIdx.x;
    const int cg = blockIdx.x & 1;
    const int stride = gridDim.x >> 1;
    const int t0 = blockIdx.x >> 1;
    const uint32_t sb = smem_u32(smem);

    // ---- stage W half once (single fp16 part) ----
    for (int i = tid; i < HALFN * 17; i += 256) {
        int r = i / 17, c = i - r * 17;
        const uint8_t* gp =
            (const uint8_t*)(Wimg + (size_t)(cg * HALFN + r) * WST) + c * 16;
        *(uint4*)(smem + OFF_W + r * (WST * 2) + c * 16) = *(const uint4*)gp;
    }

    // ---- async A staging (hi + lo parts), 64-row tile ----
    auto stageA = [&](int tile, int buf) {
        const int m0 = tile * MT;
        const uint32_t base = sb + buf * (2 * ABYTES);
        for (int i = tid; i < 2048; i += 256) {
            int part = i >> 10;
            int r = (i >> 4) & 63;
            int c = i & 15;
            int row = m0 + r;
            const __half* gp = (part ? Al : Ah) + (size_t)row * K_DIM + c * 8;
            cp_async16(base + part * ABYTES + r * (WST * 2) + c * 16, gp,
                       (row < nrows) ? 16 : 0);
        }
        asm volatile("cp.async.commit_group;" ::: "memory");
    };

    const int wid = tid >> 5, lane = tid & 31;
    const int qid = lane >> 2, tig = lane & 3;
    const int rwarp = (wid & 3) * 16;
    const int colsub = (wid >> 2) * (HALFN / 2);

    const int arow = rwarp + (lane & 15);
    const uint32_t aaddr = sb + (uint32_t)arow * (WST * 2) + ((uint32_t)(lane >> 4) << 4);
    const int nrl = colsub + (lane & 7) + ((lane >> 4) << 3);
    const uint32_t bbase = sb + OFF_W + (uint32_t)nrl * (WST * 2) +
                           ((uint32_t)((lane >> 3) & 1) << 4);

    if (t0 < ntiles) stageA(t0, 0);
    int cur = 0;
    for (int tile = t0; tile < ntiles; tile += stride) {
        int nxt = tile + stride;
        if (nxt < ntiles) {
            stageA(nxt, cur ^ 1);
            asm volatile("cp.async.wait_group 1;" ::: "memory");
        } else {
            asm volatile("cp.async.wait_group 0;" ::: "memory");
        }
        __syncthreads();

        float acc[TILES][4];
#pragma unroll
        for (int t = 0; t < TILES; t++)
#pragma unroll
            for (int q = 0; q < 4; q++) acc[t][q] = 0.f;

        const uint32_t aH = aaddr + cur * (2 * ABYTES);
        const uint32_t aL = aH + ABYTES;

        // fused mainloop: C += Ah*W + Al*W per k-step (W frags shared)
#pragma unroll 4
        for (int k0 = 0; k0 < K_DIM; k0 += 16) {
            uint32_t h0, h1, h2, h3, l0, l1, l2, l3;
            ldsm_x4(h0, h1, h2, h3, aH + k0 * 2);
            ldsm_x4(l0, l1, l2, l3, aL + k0 * 2);
#pragma unroll
            for (int tp = 0; tp < TILES / 2; tp++) {
                const uint32_t boff = tp * (16 * WST * 2) + k0 * 2;
                uint32_t w0, w1, w2, w3;
                ldsm_x4(w0, w1, w2, w3, bbase + boff);
                mma_f16(acc[2 * tp + 0], h0, h1, h2, h3, w0, w1);
                mma_f16(acc[2 * tp + 1], h0, h1, h2, h3, w2, w3);
                mma_f16(acc[2 * tp + 0], l0, l1, l2, l3, w0, w1);
                mma_f16(acc[2 * tp + 1], l0, l1, l2, l3, w2, w3);
            }
        }

        // epilogue: CTA writes only hs (cg=0) or only hn (cg=1), width HALFN
        const int r0 = tile * MT + rwarp + qid;
        const bool ok0 = r0 < nrows, ok1 = (r0 + 8) < nrows;
        if (cg == 0) {
#pragma unroll
            for (int t = 0; t < TILES; t++) {
                int col = colsub + t * 8 + tig * 2;
                if (ok0) *(float2*)&hs[(size_t)r0 * HALFN + col] = make_float2(acc[t][0], acc[t][1]);
                if (ok1) *(float2*)&hs[(size_t)(r0 + 8) * HALFN + col] = make_float2(acc[t][2], acc[t][3]);
            }
        } else {
#pragma unroll
            for (int t = 0; t < TILES; t++) {
                int col = colsub + t * 8 + tig * 2;
                if (ok0) *(uint32_t*)&hn[(size_t)r0 * HALFN + col] = pack_hf2(acc[t][0], acc[t][1]);
                if (ok1) *(uint32_t*)&hn[(size_t)(r0 + 8) * HALFN + col] = pack_hf2(acc[t][2], acc[t][3]);
            }
        }
        __syncthreads();  // all warps done reading buf before it is re-filled
        cur ^= 1;
    }
}

// ---------------- aggregation: warp per node, 8-wide MLP ----------------
// v = hs[i] + inv_deg[i] * sum_{j in N(i)} hn[j] + b   (hn fp16)
// MODE 1: relu(v) -> fp16 hi/lo (g_ah/g_al);  MODE 0: v -> fp32 out
template <int W, int MODE>
__global__ void k_agg(const float* __restrict__ hs, const __half* __restrict__ hn,
                      const float* __restrict__ bias, float* __restrict__ outf, int n) {
    constexpr int V = W / 32;
    int w = (blockIdx.x * blockDim.x + threadIdx.x) >> 5;
    if (w >= n) return;
    int lane = threadIdx.x & 31;

    float acc[V];
#pragma unroll
    for (int c = 0; c < V; c++) acc[c] = 0.f;

    const int start = g_roff[w];
    const int d = g_deg[w];
    const int* __restrict__ cp = g_csr + start;
    int t = 0;
#pragma unroll 1
    for (; t + 8 <= d; t += 8) {
        int j[8];
#pragma unroll
        for (int q = 0; q < 8; q++) j[q] = __ldg(cp + t + q);
        float v[8][V];
#pragma unroll
        for (int q = 0; q < 8; q++)
            hload<V>(v[q], &hn[(size_t)j[q] * W + lane * V]);
#pragma unroll
        for (int q = 0; q < 8; q++)
#pragma unroll
            for (int c = 0; c < V; c++) acc[c] += v[q][c];
    }
    if (t + 4 <= d) {
        int j[4];
#pragma unroll
        for (int q = 0; q < 4; q++) j[q] = __ldg(cp + t + q);
        float v[4][V];
#pragma unroll
        for (int q = 0; q < 4; q++)
            hload<V>(v[q], &hn[(size_t)j[q] * W + lane * V]);
#pragma unroll
        for (int q = 0; q < 4; q++)
#pragma unroll
            for (int c = 0; c < V; c++) acc[c] += v[q][c];
        t += 4;
    }
    for (; t < d; t++) {
        int jj = __ldg(cp + t);
        float vv[V];
        hload<V>(vv, &hn[(size_t)jj * W + lane * V]);
#pragma unroll
        for (int c = 0; c < V; c++) acc[c] += vv[c];
    }

    float inv = g_inv[w];
    float sf[V], bb[V], o[V];
    vload<V>(sf, &hs[(size_t)w * W + lane * V]);
    vload<V>(bb, &bias[lane * V]);
#pragma unroll
    for (int c = 0; c < V; c++) {
        float v = fmaf(inv, acc[c], sf[c]) + bb[c];
        o[c] = (MODE == 1) ? fmaxf(v, 0.f) : v;
    }
    if constexpr (MODE == 1) {
        float h[V], l[V];
#pragma unroll
        for (int c = 0; c < V; c++) split_hf(o[c], h[c], l[c]);
        *(uint2*)(g_ah + (size_t)w * W + lane * V) = make_uint2(pack_hf2(h[0], h[1]), pack_hf2(h[2], h[3]));
        *(uint2*)(g_al + (size_t)w * W + lane * V) = make_uint2(pack_hf2(l[0], l[1]), pack_hf2(l[2], l[3]));
    } else {
        if constexpr (V == 4)
            *(float4*)(outf + (size_t)w * W + lane * V) = make_float4(o[0], o[1], o[2], o[3]);
        else
            *(float2*)(outf + (size_t)w * W + lane * V) = make_float2(o[0], o[1]);
    }
}

// ---------------------------------------------------------------------------
extern "C" void kernel_launch(void* const* d_in, const int* in_sizes, int n_in,
                              void* d_out, int out_size) {
    const float* x   = (const float*)d_in[0];
    const int*   src = (const int*)d_in[1];
    const int*   dst = (const int*)d_in[2];
    const float* ws0 = (const float*)d_in[3];
    const float* wn0 = (const float*)d_in[4];
    const float* b0  = (const float*)d_in[5];
    const float* ws1 = (const float*)d_in[6];
    const float* wn1 = (const float*)d_in[7];
    const float* b1  = (const float*)d_in[8];
    const float* ws2 = (const float*)d_in[9];
    const float* wn2 = (const float*)d_in[10];
    const float* b2  = (const float*)d_in[11];

    const int n = in_sizes[0] / K_DIM;
    const int E = in_sizes[1];

    void *p_deg, *p_hs, *p_hn, *p_ah, *p_al, *p_w;
    cudaGetSymbolAddress(&p_deg, g_deg);
    cudaGetSymbolAddress(&p_hs, g_hs);
    cudaGetSymbolAddress(&p_hn, g_hn);
    cudaGetSymbolAddress(&p_ah, g_ah);
    cudaGetSymbolAddress(&p_al, g_al);
    cudaGetSymbolAddress(&p_w, g_wpad);
    float* hs = (float*)p_hs;
    __half* hn = (__half*)p_hn;
    const __half* ah = (const __half*)p_ah;
    const __half* al = (const __half*)p_al;
    __half* wimg = (__half*)p_w;
    constexpr size_t WSLOT = WPART;

    static cudaStream_t s2 = nullptr;
    static cudaEvent_t evF = nullptr, evJ = nullptr;
    if (!s2) {
        cudaStreamCreateWithFlags(&s2, cudaStreamNonBlocking);
        cudaEventCreateWithFlags(&evF, cudaEventDisableTiming);
        cudaEventCreateWithFlags(&evJ, cudaEventDisableTiming);
    }

    constexpr int ABYTES = MT * WST * 2;
    constexpr int SMEM256 = 4 * ABYTES + 128 * WST * 2;  // 104448
    constexpr int SMEM128 = 4 * ABYTES + 64 * WST * 2;   // 87040
    cudaFuncSetAttribute(k_gemm_mma<256>, cudaFuncAttributeMaxDynamicSharedMemorySize, SMEM256);
    cudaFuncSetAttribute(k_gemm_mma<128>, cudaFuncAttributeMaxDynamicSharedMemorySize, SMEM128);

    const int ntiles = (n + MT - 1) / MT;
    const int gemm_grid = 296;  // 2 col groups x 148
    const int eb = (E / 4 + 255) / 256;
    const int nb1 = (n + 1023) / 1024;
    const int ab = (n + 7) / 8;
    const int total4 = n * (K_DIM / 4);
    const int conv_total = 81920 + total4;

    // ---- fork: CSR build on s2, concurrent with conversions + gemm0 ----
    cudaEventRecord(evF, 0);
    cudaStreamWaitEvent(s2, evF, 0);
    cudaMemsetAsync(p_deg, 0, n * sizeof(int), s2);
    k_count<<<eb, 256, 0, s2>>>(dst, E);
    k_scan1<<<nb1, 256, 0, s2>>>(n);
    k_scan23<<<(n + 255) / 256, 256, 0, s2>>>(n, nb1);
    k_fill<<<eb, 256, 0, s2>>>(src, dst, E);
    cudaEventRecord(evJ, s2);

    // main stream: merged conversions, layer-0 GEMM
    k_conv_all<<<(conv_total + 255) / 256, 256>>>(ws0, wn0, ws1, wn1, ws2, wn2, x, total4);
    k_gemm_mma<256><<<gemm_grid, 256, SMEM256>>>(ah, al, wimg + 0 * WSLOT, hs, hn, n, ntiles);

    // ---- join: agg0 needs CSR + gemm0 ----
    cudaStreamWaitEvent(0, evJ, 0);
    k_agg<128, 1><<<ab, 256>>>(hs, hn, b0, nullptr, n);
    // layer 1
    k_gemm_mma<256><<<gemm_grid, 256, SMEM256>>>(ah, al, wimg + 1 * WSLOT, hs, hn, n, ntiles);
    k_agg<128, 1><<<ab, 256>>>(hs, hn, b1, nullptr, n);
    // layer 2 (64-wide halves, no relu, fp32 out)
    k_gemm_mma<128><<<gemm_grid, 256, SMEM128>>>(ah, al, wimg + 2 * WSLOT, hs, hn, n, ntiles);
    k_agg<64, 0><<<ab, 256>>>(hs, hn, b2, (float*)d_out, n);
}

// round 13
// speedup vs baseline: 1.6833x; 1.0979x over previous
#include <cuda_runtime.h>
#include <cuda_bf16.h>
#include <cuda_fp16.h>
#include <cstdint>

// ---------------------------------------------------------------------------
// GraphSAGE 3-layer forward, GB300 sm_103a (compute_103 PTX -> mma.sync/HMMA).
//   layer: out = h @ Ws + (segmean_dst h[src]) @ Wn + b  (+relu layers 0,1)
// R13 = R12 with single-pass fp16 GEMM (A fp16-rounded; error budget holds):
//   - C = A16 @ W16, one pass -> MMA + LDSM + staging traffic halve
//   - 3 CTAs/SM (69.6 KB smem each), __launch_bounds__(256,3)
//   - g_al eliminated; agg epilogue writes single fp16 activation image
//   Core kept: column-split persistent GEMM, cp.async double-buffer,
//   vectorized CSR on forked stream, 8-wide-MLP warp-per-node agg.
// ---------------------------------------------------------------------------

#define DINL __device__ __forceinline__

constexpr int NODES_MAX = 100000;
constexpr int EDGES_MAX = 1600000;
constexpr int K_DIM = 128;
constexpr int WST = 136;                 // padded stride (fp16 elems) = 272B
constexpr int WPART = 256 * WST;         // weight image stride (elems)
constexpr int MT = 64;                   // GEMM row-tile

// scratch (__device__ globals; no allocs allowed)
__device__ int   g_deg[NODES_MAX];
__device__ int   g_roff[NODES_MAX];
__device__ int   g_cursor[NODES_MAX];
__device__ int   g_bsums[256];
__device__ int   g_csr[EDGES_MAX];
__device__ float g_inv[NODES_MAX];
__device__ __align__(16) float g_hs[(size_t)NODES_MAX * 128];
__device__ __align__(16) __half g_hn[(size_t)NODES_MAX * 128];
__device__ __align__(16) __half g_ah[(size_t)NODES_MAX * 128];
// per layer: single fp16 part = [N up to 256][WST] (N-major)
__device__ __align__(16) __half g_wpad[3][WPART];

// ---------------- helpers ----------------
DINL uint32_t smem_u32(const void* p) {
    uint32_t a;
    asm("{ .reg .u64 t; cvta.to.shared.u64 t, %1; cvt.u32.u64 %0, t; }"
        : "=r"(a) : "l"(p));
    return a;
}
DINL uint32_t pack_hf2(float a, float b) {
    __half2 t = __floats2half2_rn(a, b);
    return *(uint32_t*)&t;
}
DINL float2 hf2f(uint32_t u) {
    __half2 h = *reinterpret_cast<__half2*>(&u);
    return __half22float2(h);
}
DINL void mma_f16(float (&d)[4], uint32_t a0, uint32_t a1, uint32_t a2, uint32_t a3,
                  uint32_t b0, uint32_t b1) {
    asm volatile(
        "mma.sync.aligned.m16n8k16.row.col.f32.f16.f16.f32 "
        "{%0,%1,%2,%3}, {%4,%5,%6,%7}, {%8,%9}, {%0,%1,%2,%3};"
        : "+f"(d[0]), "+f"(d[1]), "+f"(d[2]), "+f"(d[3])
        : "r"(a0), "r"(a1), "r"(a2), "r"(a3), "r"(b0), "r"(b1));
}
DINL void ldsm_x4(uint32_t& r0, uint32_t& r1, uint32_t& r2, uint32_t& r3, uint32_t addr) {
    asm volatile("ldmatrix.sync.aligned.m8n8.x4.shared.b16 {%0,%1,%2,%3}, [%4];"
                 : "=r"(r0), "=r"(r1), "=r"(r2), "=r"(r3) : "r"(addr));
}
DINL void cp_async16(uint32_t saddr, const void* gptr, int sz) {
    asm volatile("cp.async.cg.shared.global [%0], [%1], 16, %2;"
                 :: "r"(saddr), "l"(gptr), "r"(sz));
}

template <int V>
DINL void vload(float (&v)[V], const float* p) {
    if constexpr (V == 4) {
        float4 t = *(const float4*)p;
        v[0] = t.x; v[1] = t.y; v[2] = t.z; v[3] = t.w;
    } else {
        float2 t = *(const float2*)p;
        v[0] = t.x; v[1] = t.y;
    }
}
template <int V>
DINL void hload(float (&v)[V], const __half* p) {
    if constexpr (V == 4) {
        uint2 u = *(const uint2*)p;
        float2 x = hf2f(u.x), y = hf2f(u.y);
        v[0] = x.x; v[1] = x.y; v[2] = y.x; v[3] = y.y;
    } else {
        uint32_t u = *(const uint32_t*)p;
        float2 x = hf2f(u);
        v[0] = x.x; v[1] = x.y;
    }
}

// ---------------- CSR build ----------------
__global__ void k_count(const int* __restrict__ dst, int E) {
    int i = blockIdx.x * 256 + threadIdx.x;
    int E4 = E >> 2;
    if (i < E4) {
        int4 d = *(const int4*)(dst + i * 4);
        atomicAdd(&g_deg[d.x], 1);
        atomicAdd(&g_deg[d.y], 1);
        atomicAdd(&g_deg[d.z], 1);
        atomicAdd(&g_deg[d.w], 1);
    }
    int t = E4 * 4 + i;
    if (t < E) atomicAdd(&g_deg[dst[t]], 1);
}

__global__ void k_scan1(int n) {
    __shared__ int sh[256];
    int t = threadIdx.x;
    int i0 = blockIdx.x * 1024 + t * 4;
    int v0 = (i0 + 0 < n) ? g_deg[i0 + 0] : 0;
    int v1 = (i0 + 1 < n) ? g_deg[i0 + 1] : 0;
    int v2 = (i0 + 2 < n) ? g_deg[i0 + 2] : 0;
    int v3 = (i0 + 3 < n) ? g_deg[i0 + 3] : 0;
    int p1 = v0, p2 = v0 + v1, p3 = p2 + v2, tot = p3 + v3;
    sh[t] = tot;
    __syncthreads();
    int incl = tot;
    for (int off = 1; off < 256; off <<= 1) {
        int x = (t >= off) ? sh[t - off] : 0;
        __syncthreads();
        incl += x;
        sh[t] = incl;
        __syncthreads();
    }
    int ex = incl - tot;
    if (i0 + 0 < n) g_roff[i0 + 0] = ex;
    if (i0 + 1 < n) g_roff[i0 + 1] = ex + p1;
    if (i0 + 2 < n) g_roff[i0 + 2] = ex + p2;
    if (i0 + 3 < n) g_roff[i0 + 3] = ex + p3;
    if (t == 255) g_bsums[blockIdx.x] = incl;
}

// merged scan2+scan3: every block redundantly scans g_bsums (nb <= 256)
__global__ void k_scan23(int n, int nb) {
    __shared__ int sh[256];
    __shared__ int ex[256];
    int t = threadIdx.x;
    int v = (t < nb) ? g_bsums[t] : 0;
    sh[t] = v;
    __syncthreads();
    int incl = v;
    for (int off = 1; off < 256; off <<= 1) {
        int x = (t >= off) ? sh[t - off] : 0;
        __syncthreads();
        incl += x;
        sh[t] = incl;
        __syncthreads();
    }
    ex[t] = incl - v;
    __syncthreads();
    int i = blockIdx.x * 256 + t;
    if (i >= n) return;
    int r = g_roff[i] + ex[i >> 10];
    g_roff[i] = r;
    g_cursor[i] = r;
    g_inv[i] = 1.0f / fmaxf((float)g_deg[i], 1.0f);
}

__global__ void k_fill(const int* __restrict__ src, const int* __restrict__ dst, int E) {
    int i = blockIdx.x * 256 + threadIdx.x;
    int E4 = E >> 2;
    if (i < E4) {
        int4 d = *(const int4*)(dst + i * 4);
        int4 s = *(const int4*)(src + i * 4);
        int p0 = atomicAdd(&g_cursor[d.x], 1);
        int p1 = atomicAdd(&g_cursor[d.y], 1);
        int p2 = atomicAdd(&g_cursor[d.z], 1);
        int p3 = atomicAdd(&g_cursor[d.w], 1);
        g_csr[p0] = s.x; g_csr[p1] = s.y; g_csr[p2] = s.z; g_csr[p3] = s.w;
    }
    int t = E4 * 4 + i;
    if (t < E) {
        int p = atomicAdd(&g_cursor[dst[t]], 1);
        g_csr[p] = src[t];
    }
}

// ---------------- merged conversions: weights (fp16 images) + x (fp16) ----------------
// idx < 81920: weight element; else x float4 element (idx - 81920 < total4)
__global__ void k_conv_all(const float* __restrict__ ws0, const float* __restrict__ wn0,
                           const float* __restrict__ ws1, const float* __restrict__ wn1,
                           const float* __restrict__ ws2, const float* __restrict__ wn2,
                           const float* __restrict__ x, int total4) {
    int idx = blockIdx.x * 256 + threadIdx.x;
    if (idx < 81920) {
        int NOUT;
        const float *ws, *wn;
        __half* img;
        if (idx < 32768) { NOUT = 256; ws = ws0; wn = wn0; img = g_wpad[0]; }
        else if (idx < 65536) { idx -= 32768; NOUT = 256; ws = ws1; wn = wn1; img = g_wpad[1]; }
        else { idx -= 65536; NOUT = 128; ws = ws2; wn = wn2; img = g_wpad[2]; }
        const int HALF = NOUT / 2;
        int nrow = idx / K_DIM, k = idx % K_DIM;
        float v = (nrow < HALF) ? ws[k * HALF + nrow] : wn[k * HALF + (nrow - HALF)];
        img[nrow * WST + k] = __float2half(v);
    } else {
        int i = idx - 81920;
        if (i >= total4) return;
        float4 v = *(const float4*)(x + (size_t)i * 4);
        *(uint2*)(g_ah + (size_t)i * 4) =
            make_uint2(pack_hf2(v.x, v.y), pack_hf2(v.z, v.w));
    }
}

// ---------------- column-split persistent GEMM, fp16 single-pass, 3 CTA/SM ----------------
// grid = 296: cg = bid&1 selects output-column half (0 -> hs fp32, 1 -> hn fp16),
// t0 = bid>>1, stride 148. 64-row tiles, 256 threads = 8 warps =
// 4 row-strips(16) x 2 col subgroups of HALFN/2. C = A16 @ W16.
template <int NOUT>
__global__ void __launch_bounds__(256, 3)
k_gemm_mma(const __half* __restrict__ Ah,
           const __half* __restrict__ Wimg, float* __restrict__ hs,
           __half* __restrict__ hn, int nrows, int ntiles) {
    constexpr int HALFN = NOUT / 2;           // output width of each dest
    constexpr int ABYTES = MT * WST * 2;      // 17408 per A buffer
    constexpr int OFF_W = 2 * ABYTES;         // A: 2 bufs x 1 part
    constexpr int TILES = HALFN / 16;         // n8 tiles per warp
    extern __shared__ __align__(16) uint8_t smem[];

    const int tid = threadIdx.x;
    const int cg = blockIdx.x & 1;
    const int stride = gridDim.x >> 1;
    const int t0 = blockIdx.x >> 1;
    const uint32_t sb = smem_u32(smem);

    // ---- stage W half once ----
    for (int i = tid; i < HALFN * 17; i += 256) {
        int r = i / 17, c = i - r * 17;
        const uint8_t* gp =
            (const uint8_t*)(Wimg + (size_t)(cg * HALFN + r) * WST) + c * 16;
        *(uint4*)(smem + OFF_W + r * (WST * 2) + c * 16) = *(const uint4*)gp;
    }

    // ---- async A staging (single fp16 part), 64-row tile ----
    auto stageA = [&](int tile, int buf) {
        const int m0 = tile * MT;
        const uint32_t base = sb + buf * ABYTES;
        for (int i = tid; i < 1024; i += 256) {
            int r = i >> 4;
            int c = i & 15;
            int row = m0 + r;
            const __half* gp = Ah + (size_t)row * K_DIM + c * 8;
            cp_async16(base + r * (WST * 2) + c * 16, gp,
                       (row < nrows) ? 16 : 0);
        }
        asm volatile("cp.async.commit_group;" ::: "memory");
    };

    const int wid = tid >> 5, lane = tid & 31;
    const int qid = lane >> 2, tig = lane & 3;
    const int rwarp = (wid & 3) * 16;
    const int colsub = (wid >> 2) * (HALFN / 2);

    const int arow = rwarp + (lane & 15);
    const uint32_t aaddr = sb + (uint32_t)arow * (WST * 2) + ((uint32_t)(lane >> 4) << 4);
    const int nrl = colsub + (lane & 7) + ((lane >> 4) << 3);
    const uint32_t bbase = sb + OFF_W + (uint32_t)nrl * (WST * 2) +
                           ((uint32_t)((lane >> 3) & 1) << 4);

    if (t0 < ntiles) stageA(t0, 0);
    int cur = 0;
    for (int tile = t0; tile < ntiles; tile += stride) {
        int nxt = tile + stride;
        if (nxt < ntiles) {
            stageA(nxt, cur ^ 1);
            asm volatile("cp.async.wait_group 1;" ::: "memory");
        } else {
            asm volatile("cp.async.wait_group 0;" ::: "memory");
        }
        __syncthreads();

        float acc[TILES][4];
#pragma unroll
        for (int t = 0; t < TILES; t++)
#pragma unroll
            for (int q = 0; q < 4; q++) acc[t][q] = 0.f;

        const uint32_t aP = aaddr + cur * ABYTES;

        // single-pass mainloop: C += A*W per k-step
#pragma unroll 4
        for (int k0 = 0; k0 < K_DIM; k0 += 16) {
            uint32_t a0, a1, a2, a3;
            ldsm_x4(a0, a1, a2, a3, aP + k0 * 2);
#pragma unroll
            for (int tp = 0; tp < TILES / 2; tp++) {
                const uint32_t boff = tp * (16 * WST * 2) + k0 * 2;
                uint32_t w0, w1, w2, w3;
                ldsm_x4(w0, w1, w2, w3, bbase + boff);
                mma_f16(acc[2 * tp + 0], a0, a1, a2, a3, w0, w1);
                mma_f16(acc[2 * tp + 1], a0, a1, a2, a3, w2, w3);
            }
        }

        // epilogue: CTA writes only hs (cg=0) or only hn (cg=1), width HALFN
        const int r0 = tile * MT + rwarp + qid;
        const bool ok0 = r0 < nrows, ok1 = (r0 + 8) < nrows;
        if (cg == 0) {
#pragma unroll
            for (int t = 0; t < TILES; t++) {
                int col = colsub + t * 8 + tig * 2;
                if (ok0) *(float2*)&hs[(size_t)r0 * HALFN + col] = make_float2(acc[t][0], acc[t][1]);
                if (ok1) *(float2*)&hs[(size_t)(r0 + 8) * HALFN + col] = make_float2(acc[t][2], acc[t][3]);
            }
        } else {
#pragma unroll
            for (int t = 0; t < TILES; t++) {
                int col = colsub + t * 8 + tig * 2;
                if (ok0) *(uint32_t*)&hn[(size_t)r0 * HALFN + col] = pack_hf2(acc[t][0], acc[t][1]);
                if (ok1) *(uint32_t*)&hn[(size_t)(r0 + 8) * HALFN + col] = pack_hf2(acc[t][2], acc[t][3]);
            }
        }
        __syncthreads();  // all warps done reading buf before it is re-filled
        cur ^= 1;
    }
}

// ---------------- aggregation: warp per node, 8-wide MLP ----------------
// v = hs[i] + inv_deg[i] * sum_{j in N(i)} hn[j] + b   (hn fp16)
// MODE 1: relu(v) -> fp16 (g_ah);  MODE 0: v -> fp32 out
template <int W, int MODE>
__global__ void k_agg(const float* __restrict__ hs, const __half* __restrict__ hn,
                      const float* __restrict__ bias, float* __restrict__ outf, int n) {
    constexpr int V = W / 32;
    int w = (blockIdx.x * blockDim.x + threadIdx.x) >> 5;
    if (w >= n) return;
    int lane = threadIdx.x & 31;

    float acc[V];
#pragma unroll
    for (int c = 0; c < V; c++) acc[c] = 0.f;

    const int start = g_roff[w];
    const int d = g_deg[w];
    const int* __restrict__ cp = g_csr + start;
    int t = 0;
#pragma unroll 1
    for (; t + 8 <= d; t += 8) {
        int j[8];
#pragma unroll
        for (int q = 0; q < 8; q++) j[q] = __ldg(cp + t + q);
        float v[8][V];
#pragma unroll
        for (int q = 0; q < 8; q++)
            hload<V>(v[q], &hn[(size_t)j[q] * W + lane * V]);
#pragma unroll
        for (int q = 0; q < 8; q++)
#pragma unroll
            for (int c = 0; c < V; c++) acc[c] += v[q][c];
    }
    if (t + 4 <= d) {
        int j[4];
#pragma unroll
        for (int q = 0; q < 4; q++) j[q] = __ldg(cp + t + q);
        float v[4][V];
#pragma unroll
        for (int q = 0; q < 4; q++)
            hload<V>(v[q], &hn[(size_t)j[q] * W + lane * V]);
#pragma unroll
        for (int q = 0; q < 4; q++)
#pragma unroll
            for (int c = 0; c < V; c++) acc[c] += v[q][c];
        t += 4;
    }
    for (; t < d; t++) {
        int jj = __ldg(cp + t);
        float vv[V];
        hload<V>(vv, &hn[(size_t)jj * W + lane * V]);
#pragma unroll
        for (int c = 0; c < V; c++) acc[c] += vv[c];
    }

    float inv = g_inv[w];
    float sf[V], bb[V], o[V];
    vload<V>(sf, &hs[(size_t)w * W + lane * V]);
    vload<V>(bb, &bias[lane * V]);
#pragma unroll
    for (int c = 0; c < V; c++) {
        float v = fmaf(inv, acc[c], sf[c]) + bb[c];
        o[c] = (MODE == 1) ? fmaxf(v, 0.f) : v;
    }
    if constexpr (MODE == 1) {
        *(uint2*)(g_ah + (size_t)w * W + lane * V) =
            make_uint2(pack_hf2(o[0], o[1]), pack_hf2(o[2], o[3]));
    } else {
        if constexpr (V == 4)
            *(float4*)(outf + (size_t)w * W + lane * V) = make_float4(o[0], o[1], o[2], o[3]);
        else
            *(float2*)(outf + (size_t)w * W + lane * V) = make_float2(o[0], o[1]);
    }
}

// ---------------------------------------------------------------------------
extern "C" void kernel_launch(void* const* d_in, const int* in_sizes, int n_in,
                              void* d_out, int out_size) {
    const float* x   = (const float*)d_in[0];
    const int*   src = (const int*)d_in[1];
    const int*   dst = (const int*)d_in[2];
    const float* ws0 = (const float*)d_in[3];
    const float* wn0 = (const float*)d_in[4];
    const float* b0  = (const float*)d_in[5];
    const float* ws1 = (const float*)d_in[6];
    const float* wn1 = (const float*)d_in[7];
    const float* b1  = (const float*)d_in[8];
    const float* ws2 = (const float*)d_in[9];
    const float* wn2 = (const float*)d_in[10];
    const float* b2  = (const float*)d_in[11];

    const int n = in_sizes[0] / K_DIM;
    const int E = in_sizes[1];

    void *p_deg, *p_hs, *p_hn, *p_ah, *p_w;
    cudaGetSymbolAddress(&p_deg, g_deg);
    cudaGetSymbolAddress(&p_hs, g_hs);
    cudaGetSymbolAddress(&p_hn, g_hn);
    cudaGetSymbolAddress(&p_ah, g_ah);
    cudaGetSymbolAddress(&p_w, g_wpad);
    float* hs = (float*)p_hs;
    __half* hn = (__half*)p_hn;
    const __half* ah = (const __half*)p_ah;
    __half* wimg = (__half*)p_w;
    constexpr size_t WSLOT = WPART;

    static cudaStream_t s2 = nullptr;
    static cudaEvent_t evF = nullptr, evJ = nullptr;
    if (!s2) {
        cudaStreamCreateWithFlags(&s2, cudaStreamNonBlocking);
        cudaEventCreateWithFlags(&evF, cudaEventDisableTiming);
        cudaEventCreateWithFlags(&evJ, cudaEventDisableTiming);
    }

    constexpr int ABYTES = MT * WST * 2;
    constexpr int SMEM256 = 2 * ABYTES + 128 * WST * 2;  // 69632
    constexpr int SMEM128 = 2 * ABYTES + 64 * WST * 2;   // 52224
    cudaFuncSetAttribute(k_gemm_mma<256>, cudaFuncAttributeMaxDynamicSharedMemorySize, SMEM256);
    cudaFuncSetAttribute(k_gemm_mma<128>, cudaFuncAttributeMaxDynamicSharedMemorySize, SMEM128);

    const int ntiles = (n + MT - 1) / MT;
    const int gemm_grid = 296;  // 2 col groups x 148
    const int eb = (E / 4 + 255) / 256;
    const int nb1 = (n + 1023) / 1024;
    const int ab = (n + 7) / 8;
    const int total4 = n * (K_DIM / 4);
    const int conv_total = 81920 + total4;

    // ---- fork: CSR build on s2, concurrent with conversions + gemm0 ----
    cudaEventRecord(evF, 0);
    cudaStreamWaitEvent(s2, evF, 0);
    cudaMemsetAsync(p_deg, 0, n * sizeof(int), s2);
    k_count<<<eb, 256, 0, s2>>>(dst, E);
    k_scan1<<<nb1, 256, 0, s2>>>(n);
    k_scan23<<<(n + 255) / 256, 256, 0, s2>>>(n, nb1);
    k_fill<<<eb, 256, 0, s2>>>(src, dst, E);
    cudaEventRecord(evJ, s2);

    // main stream: merged conversions, layer-0 GEMM
    k_conv_all<<<(conv_total + 255) / 256, 256>>>(ws0, wn0, ws1, wn1, ws2, wn2, x, total4);
    k_gemm_mma<256><<<gemm_grid, 256, SMEM256>>>(ah, wimg + 0 * WSLOT, hs, hn, n, ntiles);

    // ---- join: agg0 needs CSR + gemm0 ----
    cudaStreamWaitEvent(0, evJ, 0);
    k_agg<128, 1><<<ab, 256>>>(hs, hn, b0, nullptr, n);
    // layer 1
    k_gemm_mma<256><<<gemm_grid, 256, SMEM256>>>(ah, wimg + 1 * WSLOT, hs, hn, n, ntiles);
    k_agg<128, 1><<<ab, 256>>>(hs, hn, b1, nullptr, n);
    // layer 2 (64-wide halves, no relu, fp32 out)
    k_gemm_mma<128><<<gemm_grid, 256, SMEM128>>>(ah, wimg + 2 * WSLOT, hs, hn, n, ntiles);
    k_agg<64, 0><<<ab, 256>>>(hs, hn, b2, (float*)d_out, n);
}